// round 1
// baseline (speedup 1.0000x reference)
#include <cuda_runtime.h>
#include <math.h>
#include <complex>
#include <cstring>

// ============================================================================
// FullyConnectedTensorProduct (0e+1o+2e) x (0e+1o+2e) -> (0e+1o+2e), MUL=128
//
// out[n,w,lo,k] = PW[lo] * sum_{paths p->lo} sum_u W_p[u,w] * A_p[n,u,k]
// A_p[n,u,k]   = sum_i x1_{l1}[n,u,i] * c_p[n,i,k]
// c_p[n,i,k]   = sum_j C_p[i,j,k] * x2_{l2}[n,j]
//
// Wigner 3j constants are computed on the HOST (double precision, identical
// construction to the reference) and passed as a kernel parameter struct.
// ============================================================================

#define NPATHS 11
#define TILE_N 8
#define AST    284              // padded u-stride of A in smem (floats)
#define SC_STR 116              // padded per-row stride of c table
#define SMEM_FLOATS (128*AST + TILE_N*SC_STR)
#define SMEM_BYTES  (SMEM_FLOATS*4)

typedef unsigned long long ull;

struct Params {
    float C[363];    // all 11 w3j tensors (row-major i,j,k), scaled by PW[lo]
    int4  cmap[115]; // per c-coeff: {base into C, nj, jstride, x2 base}
};

__device__ __forceinline__ ull ffma2(ull a, ull b, ull c) {
    ull d;
    asm("fma.rn.f32x2 %0, %1, %2, %3;" : "=l"(d) : "l"(a), "l"(b), "l"(c));
    return d;
}

// phase-1 macro: A[u, PK..PK+L-1] for one row from x1 regs and c table
#define P1(CO, PK, AV, NI, L) {                                              \
    _Pragma("unroll")                                                        \
    for (int k = 0; k < (L); k++) {                                          \
        float s = 0.f;                                                       \
        _Pragma("unroll")                                                    \
        for (int i = 0; i < (NI); i++) s += AV[i] * c[(CO) + i*(L) + k];     \
        Au[((PK) + k) * 8] = s;                                              \
    } }

// phase-2 macro: one path's weight contraction (f32x2, 2 row-pairs/thread)
#define P2(PIDX, L, KOB, PK) {                                               \
    const float* gw = wt + (PIDX)*16384 + w;                                 \
    float wr[8];                                                             \
    _Pragma("unroll")                                                        \
    for (int j = 0; j < 8; j++) wr[j] = __ldg(gw + j*128);                   \
    _Pragma("unroll 1")                                                      \
    for (int u0 = 0; u0 < 128; u0 += 8) {                                    \
        float wn[8];                                                         \
        const int un = (u0 + 8) & 127;                                       \
        _Pragma("unroll")                                                    \
        for (int j = 0; j < 8; j++) wn[j] = __ldg(gw + (un + j)*128);        \
        _Pragma("unroll")                                                    \
        for (int j = 0; j < 8; j++) {                                        \
            ull wv;                                                          \
            asm("mov.b64 %0, {%1, %1};" : "=l"(wv)                           \
                : "r"(__float_as_uint(wr[j])));                              \
            const float* bp = sAe + (u0 + j)*AST + (PK)*8;                   \
            _Pragma("unroll")                                                \
            for (int k = 0; k < (L); k++) {                                  \
                ulonglong2 aa =                                              \
                    *reinterpret_cast<const ulonglong2*>(bp + k*8);          \
                acc0[(KOB) + k] = ffma2(aa.x, wv, acc0[(KOB) + k]);          \
                acc1[(KOB) + k] = ffma2(aa.y, wv, acc1[(KOB) + k]);          \
            }                                                                \
        }                                                                    \
        _Pragma("unroll")                                                    \
        for (int j = 0; j < 8; j++) wr[j] = wn[j];                           \
    } }

__global__ __launch_bounds__(256, 1)
void fctp_kernel(const float* __restrict__ x1, const float* __restrict__ x2,
                 const float* __restrict__ wt, float* __restrict__ out,
                 int Ntot, const Params P)
{
    extern __shared__ float smem[];
    float* sA = smem;                 // [128][AST] : A values, 8 rows packed
    float* sc = smem + 128*AST;       // [8][SC_STR]: c coefficients per row

    const int tid  = threadIdx.x;
    const int row0 = blockIdx.x * TILE_N;

    // ---- phase 0: c_p[n,i,k] = sum_j C_p[i,j,k] * x2[n,j] -----------------
    for (int t = tid; t < TILE_N*115; t += 256) {
        int n  = t / 115;
        int ci = t - n*115;
        float s = 0.f;
        if (row0 + n < Ntot) {
            int4 m = P.cmap[ci];
            const float* x2r = x2 + (size_t)(row0 + n)*9 + m.w;
            const float* Cb  = P.C + m.x;
            for (int j = 0; j < m.y; j++) s += Cb[j*m.z] * x2r[j];
        }
        sc[n*SC_STR + ci] = s;
    }
    __syncthreads();

    const int w = tid & 127;
    const int g = tid >> 7;

    // ---- phase 1: A_p[n,u,k] into smem ------------------------------------
    {
        const int u = w;
        #pragma unroll
        for (int nn = 0; nn < 4; nn++) {
            int n = 4*g + nn;
            if (row0 + n < Ntot) {
                const float* xr = x1 + (size_t)(row0 + n)*1152;
                float a0v[1], a1v[3], a2v[5];
                a0v[0] = xr[u];
                #pragma unroll
                for (int i = 0; i < 3; i++) a1v[i] = xr[128 + 3*u + i];
                #pragma unroll
                for (int i = 0; i < 5; i++) a2v[i] = xr[512 + 5*u + i];
                const float* c  = sc + n*SC_STR;
                float*       Au = sA + u*AST + n;
                P1( 0,  0, a0v, 1, 1)   // (0,0,0)
                P1( 1,  1, a0v, 1, 3)   // (0,1,1)
                P1( 4,  4, a0v, 1, 5)   // (0,2,2)
                P1( 9,  9, a1v, 3, 3)   // (1,0,1)
                P1(18, 12, a1v, 3, 1)   // (1,1,0)
                P1(21, 13, a1v, 3, 5)   // (1,1,2)
                P1(36, 18, a1v, 3, 3)   // (1,2,1)
                P1(45, 21, a2v, 5, 5)   // (2,0,2)
                P1(70, 26, a2v, 5, 3)   // (2,1,1)
                P1(85, 29, a2v, 5, 1)   // (2,2,0)
                P1(90, 30, a2v, 5, 5)   // (2,2,2)
            }
        }
    }
    __syncthreads();

    // ---- phase 2: weight contraction (f32x2 packed rows) ------------------
    ull acc0[9], acc1[9];
    #pragma unroll
    for (int i = 0; i < 9; i++) { acc0[i] = 0ull; acc1[i] = 0ull; }
    const float* sAe = sA + 4*g;

    P2( 0, 1, 0,  0)
    P2( 1, 3, 1,  1)
    P2( 2, 5, 4,  4)
    P2( 3, 3, 1,  9)
    P2( 4, 1, 0, 12)
    P2( 5, 5, 4, 13)
    P2( 6, 3, 1, 18)
    P2( 7, 5, 4, 21)
    P2( 8, 3, 1, 26)
    P2( 9, 1, 0, 29)
    P2(10, 5, 4, 30)

    // ---- epilogue ---------------------------------------------------------
    const int r0 = row0 + 4*g;
    #pragma unroll
    for (int kk = 0; kk < 9; kk++) {
        int col = (kk == 0) ? w
                : (kk < 4)  ? 128 + 3*w + (kk - 1)
                            : 512 + 5*w + (kk - 4);
        float lo0, hi0, lo1, hi1;
        asm("mov.b64 {%0, %1}, %2;" : "=f"(lo0), "=f"(hi0) : "l"(acc0[kk]));
        asm("mov.b64 {%0, %1}, %2;" : "=f"(lo1), "=f"(hi1) : "l"(acc1[kk]));
        if (r0     < Ntot) out[(size_t)(r0    )*1152 + col] = lo0;
        if (r0 + 1 < Ntot) out[(size_t)(r0 + 1)*1152 + col] = hi0;
        if (r0 + 2 < Ntot) out[(size_t)(r0 + 2)*1152 + col] = lo1;
        if (r0 + 3 < Ntot) out[(size_t)(r0 + 3)*1152 + col] = hi1;
    }
}

// ============================================================================
// Host: Wigner-3j construction (identical math to the reference, fp64)
// ============================================================================
typedef std::complex<double> cd;

static double factd(int n) { double r = 1; for (int i = 2; i <= n; i++) r *= i; return r; }

static double su2cg(int j1, int m1, int j2, int m2, int j3, int m3) {
    if (m3 != m1 + m2) return 0.0;
    int vmin = -j1 + j2 + m3; if (-j1 + m1 > vmin) vmin = -j1 + m1; if (0 > vmin) vmin = 0;
    int vmax = j2 + j3 + m1; if (j3 - j1 + j2 < vmax) vmax = j3 - j1 + j2; if (j3 + m3 < vmax) vmax = j3 + m3;
    if (vmax < vmin) return 0.0;
    double pref = (2.0*j3 + 1.0) *
        (factd(j3 + j1 - j2) * factd(j3 - j1 + j2) * factd(j1 + j2 - j3) *
         factd(j3 + m3) * factd(j3 - m3)) /
        (factd(j1 + j2 + j3 + 1) * factd(j1 - m1) * factd(j1 + m1) *
         factd(j2 - m2) * factd(j2 + m2));
    double S = 0.0;
    for (int v = vmin; v <= vmax; v++) {
        int par = v + j2 + m2;
        double sgn = (((par % 2) + 2) % 2) ? -1.0 : 1.0;
        S += sgn * (factd(j2 + j3 + m1 - v) * factd(j1 - m1 + v)) /
             (factd(v) * factd(j3 - j1 + j2 - v) * factd(j3 + m3 - v) *
              factd(v + j1 - j2 - m3));
    }
    return sqrt(pref) * S;
}

static void calcq(int l, cd q[5][5]) {
    for (int a = 0; a < 5; a++) for (int b = 0; b < 5; b++) q[a][b] = cd(0, 0);
    const double s2 = 1.0 / sqrt(2.0);
    for (int m = -l; m < 0; m++) {
        q[l + m][l - m] = cd(s2, 0);
        q[l + m][l + m] = cd(0, -s2);
    }
    q[l][l] = cd(1, 0);
    for (int m = 1; m <= l; m++) {
        double sg = (m % 2) ? -1.0 : 1.0;
        q[l + m][l + m] = cd(sg * s2, 0);
        q[l + m][l - m] = cd(0, sg * s2);
    }
    cd f = (l == 0) ? cd(1, 0) : (l == 1) ? cd(0, -1) : cd(-1, 0); // (-i)^l
    for (int a = 0; a < 5; a++) for (int b = 0; b < 5; b++) q[a][b] *= f;
}

static void calc_w3j(int l1, int l2, int l3, double* outv) {
    int d1 = 2*l1 + 1, d2 = 2*l2 + 1, d3 = 2*l3 + 1;
    double C[5][5][5];
    memset(C, 0, sizeof(C));
    for (int m1 = -l1; m1 <= l1; m1++)
        for (int m2 = -l2; m2 <= l2; m2++) {
            int m3 = m1 + m2;
            if (m3 >= -l3 && m3 <= l3)
                C[m1 + l1][m2 + l2][m3 + l3] = su2cg(l1, m1, l2, m2, l3, m3);
        }
    cd Q1[5][5], Q2[5][5], Q3[5][5];
    calcq(l1, Q1); calcq(l2, Q2); calcq(l3, Q3);
    static cd Cc[5][5][5];
    for (int j = 0; j < d1; j++)
        for (int l = 0; l < d2; l++)
            for (int m = 0; m < d3; m++) {
                cd s(0, 0);
                for (int i = 0; i < d1; i++)
                    for (int k = 0; k < d2; k++)
                        for (int n = 0; n < d3; n++)
                            s += Q1[i][j] * Q2[k][l] * std::conj(Q3[n][m]) * C[i][k][n];
                Cc[j][l][m] = s;
            }
    double nr = 0, ni = 0;
    for (int j = 0; j < d1; j++)
        for (int l = 0; l < d2; l++)
            for (int m = 0; m < d3; m++) {
                nr += Cc[j][l][m].real() * Cc[j][l][m].real();
                ni += Cc[j][l][m].imag() * Cc[j][l][m].imag();
            }
    bool useR = sqrt(nr) >= sqrt(ni);
    double nrm = sqrt(useR ? nr : ni);
    for (int j = 0; j < d1; j++)
        for (int l = 0; l < d2; l++)
            for (int m = 0; m < d3; m++)
                outv[(j*d2 + l)*d3 + m] =
                    (useR ? Cc[j][l][m].real() : Cc[j][l][m].imag()) / nrm;
}

static void build_params(Params& P) {
    static const int L1[NPATHS] = {0,0,0,1,1,1,1,2,2,2,2};
    static const int L2[NPATHS] = {0,1,2,0,1,1,2,0,1,2,2};
    static const int LO[NPATHS] = {0,1,2,1,0,2,1,2,1,0,2};
    static const int cof3[NPATHS] = {0,1,10,35,44,53,98,143,168,213,238};
    static const int x2off[3] = {0, 1, 4};
    const double pw[3] = { sqrt(1.0/384.0), sqrt(3.0/512.0), sqrt(5.0/512.0) };

    int ci = 0;
    for (int p = 0; p < NPATHS; p++) {
        int d1 = 2*L1[p] + 1, d2 = 2*L2[p] + 1, d3 = 2*LO[p] + 1;
        double buf[125];
        calc_w3j(L1[p], L2[p], LO[p], buf);
        for (int idx = 0; idx < d1*d2*d3; idx++)
            P.C[cof3[p] + idx] = (float)(buf[idx] * pw[LO[p]]);
        for (int i = 0; i < d1; i++)
            for (int k = 0; k < d3; k++) {
                P.cmap[ci] = make_int4(cof3[p] + i*d2*d3 + k, d2, d3, x2off[L2[p]]);
                ci++;
            }
    }
}

extern "C" void kernel_launch(void* const* d_in, const int* in_sizes, int n_in,
                              void* d_out, int out_size)
{
    const float* x1  = (const float*)d_in[0];
    const float* x2  = (const float*)d_in[1];
    const float* wt  = (const float*)d_in[2];
    float*       out = (float*)d_out;
    const int N = in_sizes[0] / 1152;

    Params P;
    build_params(P);

    cudaFuncSetAttribute(fctp_kernel,
                         cudaFuncAttributeMaxDynamicSharedMemorySize, SMEM_BYTES);
    const int grid = (N + TILE_N - 1) / TILE_N;
    fctp_kernel<<<grid, 256, SMEM_BYTES>>>(x1, x2, wt, out, N, P);
}

// round 2
// speedup vs baseline: 1.0017x; 1.0017x over previous
#include <cuda_runtime.h>
#include <math.h>
#include <complex>
#include <cstring>

// ============================================================================
// FullyConnectedTensorProduct (0e+1o+2e) x (0e+1o+2e) -> (0e+1o+2e), MUL=128
//
// out[n,w,lo,k] = PW[lo] * sum_{paths p->lo} sum_u W_p[u,w] * A_p[n,u,k]
// A_p[n,u,k]   = sum_i x1_{l1}[n,u,i] * c_p[n,i,k]
// c_p[n,i,k]   = sum_j C_p[i,j,k] * x2_{l2}[n,j]
//
// Wigner 3j constants are computed on the HOST (double precision, identical
// construction to the reference) and passed as a kernel parameter struct.
// ============================================================================

#define NPATHS 11
#define TILE_N 8
#define AST    284              // padded u-stride of A in smem (floats)
#define SC_STR 116              // padded per-row stride of c table
#define SMEM_FLOATS (128*AST + TILE_N*SC_STR)
#define SMEM_BYTES  (SMEM_FLOATS*4)

typedef unsigned long long ull;

struct Params {
    float C[363];    // all 11 w3j tensors (row-major i,j,k), scaled by PW[lo]
    int4  cmap[115]; // per c-coeff: {base into C, nj, jstride, x2 base}
};

__device__ __forceinline__ ull ffma2(ull a, ull b, ull c) {
    ull d;
    asm("fma.rn.f32x2 %0, %1, %2, %3;" : "=l"(d) : "l"(a), "l"(b), "l"(c));
    return d;
}

// phase-1 macro: A[u, PK..PK+L-1] for one row from x1 regs and c table
#define P1(CO, PK, AV, NI, L) {                                              \
    _Pragma("unroll")                                                        \
    for (int k = 0; k < (L); k++) {                                          \
        float s = 0.f;                                                       \
        _Pragma("unroll")                                                    \
        for (int i = 0; i < (NI); i++) s += AV[i] * c[(CO) + i*(L) + k];     \
        Au[((PK) + k) * 8] = s;                                              \
    } }

// phase-2 macro: one path's weight contraction (f32x2, 2 row-pairs/thread)
#define P2(PIDX, L, KOB, PK) {                                               \
    const float* gw = wt + (PIDX)*16384 + w;                                 \
    float wr[8];                                                             \
    _Pragma("unroll")                                                        \
    for (int j = 0; j < 8; j++) wr[j] = __ldg(gw + j*128);                   \
    _Pragma("unroll 1")                                                      \
    for (int u0 = 0; u0 < 128; u0 += 8) {                                    \
        float wn[8];                                                         \
        const int un = (u0 + 8) & 127;                                       \
        _Pragma("unroll")                                                    \
        for (int j = 0; j < 8; j++) wn[j] = __ldg(gw + (un + j)*128);        \
        _Pragma("unroll")                                                    \
        for (int j = 0; j < 8; j++) {                                        \
            ull wv;                                                          \
            asm("mov.b64 %0, {%1, %1};" : "=l"(wv)                           \
                : "r"(__float_as_uint(wr[j])));                              \
            const float* bp = sAe + (u0 + j)*AST + (PK)*8;                   \
            _Pragma("unroll")                                                \
            for (int k = 0; k < (L); k++) {                                  \
                ulonglong2 aa =                                              \
                    *reinterpret_cast<const ulonglong2*>(bp + k*8);          \
                acc0[(KOB) + k] = ffma2(aa.x, wv, acc0[(KOB) + k]);          \
                acc1[(KOB) + k] = ffma2(aa.y, wv, acc1[(KOB) + k]);          \
            }                                                                \
        }                                                                    \
        _Pragma("unroll")                                                    \
        for (int j = 0; j < 8; j++) wr[j] = wn[j];                           \
    } }

__global__ __launch_bounds__(256, 1)
void fctp_kernel(const float* __restrict__ x1, const float* __restrict__ x2,
                 const float* __restrict__ wt, float* __restrict__ out,
                 int Ntot, const Params P)
{
    extern __shared__ float smem[];
    float* sA = smem;                 // [128][AST] : A values, 8 rows packed
    float* sc = smem + 128*AST;       // [8][SC_STR]: c coefficients per row

    const int tid  = threadIdx.x;
    const int row0 = blockIdx.x * TILE_N;

    // ---- phase 0: c_p[n,i,k] = sum_j C_p[i,j,k] * x2[n,j] -----------------
    for (int t = tid; t < TILE_N*115; t += 256) {
        int n  = t / 115;
        int ci = t - n*115;
        float s = 0.f;
        if (row0 + n < Ntot) {
            int4 m = P.cmap[ci];
            const float* x2r = x2 + (size_t)(row0 + n)*9 + m.w;
            const float* Cb  = P.C + m.x;
            for (int j = 0; j < m.y; j++) s += Cb[j*m.z] * x2r[j];
        }
        sc[n*SC_STR + ci] = s;
    }
    __syncthreads();

    const int w = tid & 127;
    const int g = tid >> 7;

    // ---- phase 1: A_p[n,u,k] into smem ------------------------------------
    {
        const int u = w;
        #pragma unroll
        for (int nn = 0; nn < 4; nn++) {
            int n = 4*g + nn;
            if (row0 + n < Ntot) {
                const float* xr = x1 + (size_t)(row0 + n)*1152;
                float a0v[1], a1v[3], a2v[5];
                a0v[0] = xr[u];
                #pragma unroll
                for (int i = 0; i < 3; i++) a1v[i] = xr[128 + 3*u + i];
                #pragma unroll
                for (int i = 0; i < 5; i++) a2v[i] = xr[512 + 5*u + i];
                const float* c  = sc + n*SC_STR;
                float*       Au = sA + u*AST + n;
                P1( 0,  0, a0v, 1, 1)   // (0,0,0)
                P1( 1,  1, a0v, 1, 3)   // (0,1,1)
                P1( 4,  4, a0v, 1, 5)   // (0,2,2)
                P1( 9,  9, a1v, 3, 3)   // (1,0,1)
                P1(18, 12, a1v, 3, 1)   // (1,1,0)
                P1(21, 13, a1v, 3, 5)   // (1,1,2)
                P1(36, 18, a1v, 3, 3)   // (1,2,1)
                P1(45, 21, a2v, 5, 5)   // (2,0,2)
                P1(70, 26, a2v, 5, 3)   // (2,1,1)
                P1(85, 29, a2v, 5, 1)   // (2,2,0)
                P1(90, 30, a2v, 5, 5)   // (2,2,2)
            }
        }
    }
    __syncthreads();

    // ---- phase 2: weight contraction (f32x2 packed rows) ------------------
    ull acc0[9], acc1[9];
    #pragma unroll
    for (int i = 0; i < 9; i++) { acc0[i] = 0ull; acc1[i] = 0ull; }
    const float* sAe = sA + 4*g;

    P2( 0, 1, 0,  0)
    P2( 1, 3, 1,  1)
    P2( 2, 5, 4,  4)
    P2( 3, 3, 1,  9)
    P2( 4, 1, 0, 12)
    P2( 5, 5, 4, 13)
    P2( 6, 3, 1, 18)
    P2( 7, 5, 4, 21)
    P2( 8, 3, 1, 26)
    P2( 9, 1, 0, 29)
    P2(10, 5, 4, 30)

    // ---- epilogue ---------------------------------------------------------
    const int r0 = row0 + 4*g;
    #pragma unroll
    for (int kk = 0; kk < 9; kk++) {
        int col = (kk == 0) ? w
                : (kk < 4)  ? 128 + 3*w + (kk - 1)
                            : 512 + 5*w + (kk - 4);
        float lo0, hi0, lo1, hi1;
        asm("mov.b64 {%0, %1}, %2;" : "=f"(lo0), "=f"(hi0) : "l"(acc0[kk]));
        asm("mov.b64 {%0, %1}, %2;" : "=f"(lo1), "=f"(hi1) : "l"(acc1[kk]));
        if (r0     < Ntot) out[(size_t)(r0    )*1152 + col] = lo0;
        if (r0 + 1 < Ntot) out[(size_t)(r0 + 1)*1152 + col] = hi0;
        if (r0 + 2 < Ntot) out[(size_t)(r0 + 2)*1152 + col] = lo1;
        if (r0 + 3 < Ntot) out[(size_t)(r0 + 3)*1152 + col] = hi1;
    }
}

// ============================================================================
// Host: Wigner-3j construction (identical math to the reference, fp64)
// ============================================================================
typedef std::complex<double> cd;

static double factd(int n) { double r = 1; for (int i = 2; i <= n; i++) r *= i; return r; }

static double su2cg(int j1, int m1, int j2, int m2, int j3, int m3) {
    if (m3 != m1 + m2) return 0.0;
    int vmin = -j1 + j2 + m3; if (-j1 + m1 > vmin) vmin = -j1 + m1; if (0 > vmin) vmin = 0;
    int vmax = j2 + j3 + m1; if (j3 - j1 + j2 < vmax) vmax = j3 - j1 + j2; if (j3 + m3 < vmax) vmax = j3 + m3;
    if (vmax < vmin) return 0.0;
    double pref = (2.0*j3 + 1.0) *
        (factd(j3 + j1 - j2) * factd(j3 - j1 + j2) * factd(j1 + j2 - j3) *
         factd(j3 + m3) * factd(j3 - m3)) /
        (factd(j1 + j2 + j3 + 1) * factd(j1 - m1) * factd(j1 + m1) *
         factd(j2 - m2) * factd(j2 + m2));
    double S = 0.0;
    for (int v = vmin; v <= vmax; v++) {
        int par = v + j2 + m2;
        double sgn = (((par % 2) + 2) % 2) ? -1.0 : 1.0;
        S += sgn * (factd(j2 + j3 + m1 - v) * factd(j1 - m1 + v)) /
             (factd(v) * factd(j3 - j1 + j2 - v) * factd(j3 + m3 - v) *
              factd(v + j1 - j2 - m3));
    }
    return sqrt(pref) * S;
}

static void calcq(int l, cd q[5][5]) {
    for (int a = 0; a < 5; a++) for (int b = 0; b < 5; b++) q[a][b] = cd(0, 0);
    const double s2 = 1.0 / sqrt(2.0);
    for (int m = -l; m < 0; m++) {
        q[l + m][l - m] = cd(s2, 0);
        q[l + m][l + m] = cd(0, -s2);
    }
    q[l][l] = cd(1, 0);
    for (int m = 1; m <= l; m++) {
        double sg = (m % 2) ? -1.0 : 1.0;
        q[l + m][l + m] = cd(sg * s2, 0);
        q[l + m][l - m] = cd(0, sg * s2);
    }
    cd f = (l == 0) ? cd(1, 0) : (l == 1) ? cd(0, -1) : cd(-1, 0); // (-i)^l
    for (int a = 0; a < 5; a++) for (int b = 0; b < 5; b++) q[a][b] *= f;
}

static void calc_w3j(int l1, int l2, int l3, double* outv) {
    int d1 = 2*l1 + 1, d2 = 2*l2 + 1, d3 = 2*l3 + 1;
    double C[5][5][5];
    memset(C, 0, sizeof(C));
    for (int m1 = -l1; m1 <= l1; m1++)
        for (int m2 = -l2; m2 <= l2; m2++) {
            int m3 = m1 + m2;
            if (m3 >= -l3 && m3 <= l3)
                C[m1 + l1][m2 + l2][m3 + l3] = su2cg(l1, m1, l2, m2, l3, m3);
        }
    cd Q1[5][5], Q2[5][5], Q3[5][5];
    calcq(l1, Q1); calcq(l2, Q2); calcq(l3, Q3);
    static cd Cc[5][5][5];
    for (int j = 0; j < d1; j++)
        for (int l = 0; l < d2; l++)
            for (int m = 0; m < d3; m++) {
                cd s(0, 0);
                for (int i = 0; i < d1; i++)
                    for (int k = 0; k < d2; k++)
                        for (int n = 0; n < d3; n++)
                            s += Q1[i][j] * Q2[k][l] * std::conj(Q3[n][m]) * C[i][k][n];
                Cc[j][l][m] = s;
            }
    double nr = 0, ni = 0;
    for (int j = 0; j < d1; j++)
        for (int l = 0; l < d2; l++)
            for (int m = 0; m < d3; m++) {
                nr += Cc[j][l][m].real() * Cc[j][l][m].real();
                ni += Cc[j][l][m].imag() * Cc[j][l][m].imag();
            }
    bool useR = sqrt(nr) >= sqrt(ni);
    double nrm = sqrt(useR ? nr : ni);
    for (int j = 0; j < d1; j++)
        for (int l = 0; l < d2; l++)
            for (int m = 0; m < d3; m++)
                outv[(j*d2 + l)*d3 + m] =
                    (useR ? Cc[j][l][m].real() : Cc[j][l][m].imag()) / nrm;
}

static void build_params(Params& P) {
    static const int L1[NPATHS] = {0,0,0,1,1,1,1,2,2,2,2};
    static const int L2[NPATHS] = {0,1,2,0,1,1,2,0,1,2,2};
    static const int LO[NPATHS] = {0,1,2,1,0,2,1,2,1,0,2};
    static const int cof3[NPATHS] = {0,1,10,35,44,53,98,143,168,213,238};
    static const int x2off[3] = {0, 1, 4};
    const double pw[3] = { sqrt(1.0/384.0), sqrt(3.0/512.0), sqrt(5.0/512.0) };

    int ci = 0;
    for (int p = 0; p < NPATHS; p++) {
        int d1 = 2*L1[p] + 1, d2 = 2*L2[p] + 1, d3 = 2*LO[p] + 1;
        double buf[125];
        calc_w3j(L1[p], L2[p], LO[p], buf);
        for (int idx = 0; idx < d1*d2*d3; idx++)
            P.C[cof3[p] + idx] = (float)(buf[idx] * pw[LO[p]]);
        for (int i = 0; i < d1; i++)
            for (int k = 0; k < d3; k++) {
                P.cmap[ci] = make_int4(cof3[p] + i*d2*d3 + k, d2, d3, x2off[L2[p]]);
                ci++;
            }
    }
}

extern "C" void kernel_launch(void* const* d_in, const int* in_sizes, int n_in,
                              void* d_out, int out_size)
{
    const float* x1  = (const float*)d_in[0];
    const float* x2  = (const float*)d_in[1];
    const float* wt  = (const float*)d_in[2];
    float*       out = (float*)d_out;
    const int N = in_sizes[0] / 1152;

    Params P;
    build_params(P);

    cudaFuncSetAttribute(fctp_kernel,
                         cudaFuncAttributeMaxDynamicSharedMemorySize, SMEM_BYTES);
    const int grid = (N + TILE_N - 1) / TILE_N;
    fctp_kernel<<<grid, 256, SMEM_BYTES>>>(x1, x2, wt, out, N, P);
}